// round 8
// baseline (speedup 1.0000x reference)
#include <cuda_runtime.h>
#include <cuda_bf16.h>
#include <cstdint>
#include <math.h>

// ============================================================================
// ARDiscriminator on GB300 — round 7: R4 tiling (128x64, 2 CTAs/SM) +
// 4-stage single-sync cp.async pipeline (32-wide K slabs, SW64 swizzle) +
// WaveNet main/gate fused in one CTA with pointwise in the epilogue.
// bf16 hi/lo 3-term split numerics (proven, rel_err ~2.7e-5).
// ============================================================================

#define NFRAMES 2048

template <int N> struct ILog2 { static constexpr int v = 1 + ILog2<N / 2>::v; };
template <> struct ILog2<1> { static constexpr int v = 0; };

// ---------------- static scratch -------------------------------------------
__device__ __align__(128) __nv_bfloat16 g_pAhi[(size_t)NFRAMES * 128 * 128];
__device__ __align__(128) __nv_bfloat16 g_pAlo[(size_t)NFRAMES * 128 * 128];
__device__ __align__(128) __nv_bfloat16 g_pBhi[(size_t)NFRAMES * 64 * 128];
__device__ __align__(128) __nv_bfloat16 g_pBlo[(size_t)NFRAMES * 64 * 128];
__device__ __align__(128) float         g_H   [NFRAMES * 256];
__device__ __align__(128) __nv_bfloat16 g_Hhi [NFRAMES * 256];
__device__ __align__(128) __nv_bfloat16 g_Hlo [NFRAMES * 256];
__device__ __align__(128) float         g_Henc[2048];
// weight planes (k-reordered: k = kw*CIN + ci ; tap*256+ci for wavenet)
__device__ __align__(128) __nv_bfloat16 g_w123hi [3 * 128 * 896];
__device__ __align__(128) __nv_bfloat16 g_w123lo [3 * 128 * 896];
__device__ __align__(128) __nv_bfloat16 g_w4567hi[4 * 128 * 384];
__device__ __align__(128) __nv_bfloat16 g_w4567lo[4 * 128 * 384];
__device__ __align__(128) __nv_bfloat16 g_w8hi   [256 * 128];
__device__ __align__(128) __nv_bfloat16 g_w8lo   [256 * 128];
__device__ __align__(128) __nv_bfloat16 g_wnhi   [8 * 2 * 256 * 512];
__device__ __align__(128) __nv_bfloat16 g_wnlo   [8 * 2 * 256 * 512];

// ---------------- low-level helpers ----------------------------------------
__device__ __forceinline__ uint32_t smem_u32(const void* p) {
    uint32_t a;
    asm("{ .reg .u64 t; cvta.to.shared.u64 t, %1; cvt.u32.u64 %0, t; }"
        : "=r"(a) : "l"(p));
    return a;
}
__device__ __forceinline__ void cp16(uint32_t dst, const void* src, int sz) {
    asm volatile("cp.async.cg.shared.global [%0], [%1], 16, %2;"
                 :: "r"(dst), "l"(src), "r"(sz));
}
#define CP_COMMIT() asm volatile("cp.async.commit_group;")
#define CP_WAIT(n)  asm volatile("cp.async.wait_group %0;" :: "n"(n))

__device__ __forceinline__ void ldsm_x4(uint32_t (&r)[4], uint32_t addr) {
    asm volatile("ldmatrix.sync.aligned.m8n8.x4.shared.b16 {%0,%1,%2,%3}, [%4];"
                 : "=r"(r[0]), "=r"(r[1]), "=r"(r[2]), "=r"(r[3]) : "r"(addr));
}
__device__ __forceinline__ void ldsm_x2(uint32_t (&r)[2], uint32_t addr) {
    asm volatile("ldmatrix.sync.aligned.m8n8.x2.shared.b16 {%0,%1}, [%2];"
                 : "=r"(r[0]), "=r"(r[1]) : "r"(addr));
}
__device__ __forceinline__ void mma_bf16(float (&c)[4], const uint32_t (&a)[4],
                                         uint32_t b0, uint32_t b1) {
    asm volatile(
        "mma.sync.aligned.m16n8k16.row.col.f32.bf16.bf16.f32 "
        "{%0,%1,%2,%3}, {%4,%5,%6,%7}, {%8,%9}, {%0,%1,%2,%3};"
        : "+f"(c[0]), "+f"(c[1]), "+f"(c[2]), "+f"(c[3])
        : "r"(a[0]), "r"(a[1]), "r"(a[2]), "r"(a[3]), "r"(b0), "r"(b1));
}

// SW64 swizzle for 64B rows (8 rows x 64B atom)
__device__ __forceinline__ uint32_t sw64(uint32_t off) {
    return off ^ ((off >> 3) & 0x30);
}

__device__ __forceinline__ void split1(float v, __nv_bfloat16& h, __nv_bfloat16& l) {
    h = __float2bfloat16(v);
    l = __float2bfloat16(v - __bfloat162float(h));
}

// ---- conv stage: A 128x32k hi/lo (8+8KB) + B 64x32k hi/lo (4+4KB) ----------
static constexpr int CV_A_HI = 0;
static constexpr int CV_A_LO = 8192;
static constexpr int CV_B_HI = 16384;
static constexpr int CV_B_LO = 20480;
static constexpr int CV_BUF  = 24576;
static constexpr int CV_SMEM = 4 * CV_BUF;   // 96KB -> 2 CTAs/SM
// ---- wn stage: A 128x32k hi/lo (8+8KB) + B 32x32k hi/lo (2+2KB) ------------
static constexpr int WN_A_HI = 0;
static constexpr int WN_A_LO = 8192;
static constexpr int WN_B_HI = 16384;
static constexpr int WN_B_LO = 18432;
static constexpr int WN_BUF  = 20480;
static constexpr int WN_SMEM = 4 * WN_BUF;   // 80KB -> 2 CTAs/SM

// ---- conv compute: warp tile 32(M) x 32(N), one 32-wide K slab -------------
__device__ __forceinline__ void compute_conv(uint32_t base, int lane, int wm, int wn_,
                                             float (&c)[2][4][4]) {
#pragma unroll
    for (int kc = 0; kc < 32; kc += 16) {
        uint32_t bh[4][2], bl[4][2];
#pragma unroll
        for (int ni = 0; ni < 4; ni++) {
            uint32_t off = (wn_ + ni * 8 + (lane & 7)) * 64 +
                           (kc + ((lane >> 3) & 1) * 8) * 2;
            uint32_t swo = sw64(off);
            ldsm_x2(bh[ni], base + CV_B_HI + swo);
            ldsm_x2(bl[ni], base + CV_B_LO + swo);
        }
#pragma unroll
        for (int mi = 0; mi < 2; mi++) {
            uint32_t off = (wm + mi * 16 + (lane & 7) + ((lane >> 3) & 1) * 8) * 64 +
                           (kc + (lane >> 4) * 8) * 2;
            uint32_t swo = sw64(off);
            uint32_t ah[4], al[4];
            ldsm_x4(ah, base + CV_A_HI + swo);
            ldsm_x4(al, base + CV_A_LO + swo);
#pragma unroll
            for (int ni = 0; ni < 4; ni++) {
                mma_bf16(c[mi][ni], ah, bh[ni][0], bh[ni][1]);
                mma_bf16(c[mi][ni], ah, bl[ni][0], bl[ni][1]);
                mma_bf16(c[mi][ni], al, bh[ni][0], bh[ni][1]);
            }
        }
    }
}

// ---- wn compute: warp tile 32(M) x 16(N), one 32-wide K slab ----------------
__device__ __forceinline__ void compute_wn(uint32_t base, int lane, int wm, int wn_,
                                           float (&c)[2][2][4]) {
#pragma unroll
    for (int kc = 0; kc < 32; kc += 16) {
        uint32_t bh[2][2], bl[2][2];
#pragma unroll
        for (int ni = 0; ni < 2; ni++) {
            uint32_t off = (wn_ + ni * 8 + (lane & 7)) * 64 +
                           (kc + ((lane >> 3) & 1) * 8) * 2;
            uint32_t swo = sw64(off);
            ldsm_x2(bh[ni], base + WN_B_HI + swo);
            ldsm_x2(bl[ni], base + WN_B_LO + swo);
        }
#pragma unroll
        for (int mi = 0; mi < 2; mi++) {
            uint32_t off = (wm + mi * 16 + (lane & 7) + ((lane >> 3) & 1) * 8) * 64 +
                           (kc + (lane >> 4) * 8) * 2;
            uint32_t swo = sw64(off);
            uint32_t ah[4], al[4];
            ldsm_x4(ah, base + WN_A_HI + swo);
            ldsm_x4(al, base + WN_A_LO + swo);
#pragma unroll
            for (int ni = 0; ni < 2; ni++) {
                mma_bf16(c[mi][ni], ah, bh[ni][0], bh[ni][1]);
                mma_bf16(c[mi][ni], ah, bl[ni][0], bl[ni][1]);
                mma_bf16(c[mi][ni], al, bh[ni][0], bh[ni][1]);
            }
        }
    }
}

// ---------------- weight prep: split + k-reorder -----------------------------
__global__ void prep_weights(const float* __restrict__ w123,
                             const float* __restrict__ w4567,
                             const float* __restrict__ w8,
                             const float* __restrict__ wm,
                             const float* __restrict__ wg) {
    const int stride = gridDim.x * blockDim.x;
    const int t0 = blockIdx.x * blockDim.x + threadIdx.x;
    for (int e = t0; e < 3 * 128 * 896; e += stride) {
        int l = e / (128 * 896), r = e % (128 * 896);
        int co = r / 896, k = r % 896;
        int kw = k >> 7, ci = k & 127;
        split1(w123[((l * 128 + co) * 128 + ci) * 7 + kw], g_w123hi[e], g_w123lo[e]);
    }
    for (int e = t0; e < 4 * 128 * 384; e += stride) {
        int l = e / (128 * 384), r = e % (128 * 384);
        int co = r / 384, k = r % 384;
        int kw = k >> 7, ci = k & 127;
        split1(w4567[((l * 128 + co) * 128 + ci) * 3 + kw], g_w4567hi[e], g_w4567lo[e]);
    }
    for (int e = t0; e < 256 * 128; e += stride) {
        int co = e >> 7, ci = e & 127;
        split1(w8[co * 128 + ci], g_w8hi[e], g_w8lo[e]);
    }
    for (int e = t0; e < 8 * 2 * 256 * 512; e += stride) {
        int lz = e / (256 * 512), r = e % (256 * 512);
        int co = r / 512, k = r % 512;
        int tap = k >> 8, ci = k & 255;
        int l = lz >> 1, z = lz & 1;
        const float* w = z ? wg : wm;
        split1(w[((l * 256 + co) * 256 + ci) * 2 + tap], g_wnhi[e], g_wnlo[e]);
    }
}

// ---------------- encoder conv0 (Cin=1, K=7, s=2, pad 3) --------------------
__global__ void conv0_kernel(const float* __restrict__ x,
                             const float* __restrict__ w0) {
    __shared__ float xin[256];
    __shared__ float w0s[896];
    const int f = blockIdx.x;
    const int b = f >> 8, t = (f & 255) + 256;
    const int tid = threadIdx.x;

    xin[tid] = x[(b * 256 + tid) * 512 + t];
    for (int i = tid; i < 896; i += 256) w0s[i] = w0[i];
    __syncthreads();

    const int co = tid & 127;
    const int ph = tid >> 7;
#pragma unroll 4
    for (int u = 0; u < 64; u++) {
        int p = ph * 64 + u;
        float s = 0.f;
#pragma unroll
        for (int k = 0; k < 7; k++) {
            int ip = 2 * p + k - 3;
            float xv = (ip >= 0 && ip < 256) ? xin[ip] : 0.f;
            s = fmaf(w0s[co * 7 + k], xv, s);
        }
        s = s > 0.f ? s : 0.2f * s;
        size_t o = ((size_t)f * 128 + p) * 128 + co;
        split1(s, g_pAhi[o], g_pAlo[o]);
    }
}

// ---------------- conv-as-GEMM: 128x64, 4-stage single-sync pipeline --------
template <int KW, int PAD, int LIN, int LOUT, bool RELU, bool LAST>
__global__ __launch_bounds__(256, 2)
void conv_mma3(const __nv_bfloat16* __restrict__ in_hi,
               const __nv_bfloat16* __restrict__ in_lo,
               const __nv_bfloat16* __restrict__ w_hi,
               const __nv_bfloat16* __restrict__ w_lo,
               __nv_bfloat16* __restrict__ out_hi,
               __nv_bfloat16* __restrict__ out_lo) {
    constexpr int K = KW * 128;
    constexpr int NST = K / 32;           // >= 4 always
    constexpr int LOG = ILog2<LOUT>::v;
    extern __shared__ __align__(1024) char smem[];
    const uint32_t sb = smem_u32(smem);

    const int tid = threadIdx.x;
    const int lane = tid & 31;
    const int warp = tid >> 5;
    const int wm = (warp >> 1) * 32;
    const int wn_ = (warp & 1) * 32;
    const int col0 = blockIdx.x * 64;
    const int m0 = blockIdx.y * 128;

    float c[2][4][4];
#pragma unroll
    for (int i = 0; i < 2; i++)
#pragma unroll
        for (int j = 0; j < 4; j++)
#pragma unroll
            for (int k = 0; k < 4; k++) c[i][j][k] = 0.f;

    auto issue = [&](int s) {
        const uint32_t bo = sb + (s & 3) * CV_BUF;
        const int kw = s >> 2;
        const int ci0 = (s & 3) * 32;
        // A: 128 rows x 64B (weights, k-contiguous): 512 slots
#pragma unroll
        for (int g = 0; g < 2; g++) {
            int gi = tid + g * 256;
            int row = gi >> 2, j = gi & 3;
            uint32_t off = sw64(row * 64 + j * 16);
            size_t so = (size_t)(m0 + row) * K + s * 32 + j * 8;
            cp16(bo + CV_A_HI + off, w_hi + so, 16);
            cp16(bo + CV_A_LO + off, w_lo + so, 16);
        }
        // B: 64 rows x 64B (im2col): 256 slots
        {
            int row = tid >> 2, j = tid & 3;
            int col = col0 + row;
            int f = col >> LOG;
            int p = col & (LOUT - 1);
            int ip = 2 * p + kw - PAD;
            bool v = ((unsigned)ip < (unsigned)LIN);
            size_t so = ((size_t)f * LIN + (v ? ip : 0)) * 128 + ci0 + j * 8;
            int sz = v ? 16 : 0;
            uint32_t off = sw64(row * 64 + j * 16);
            cp16(bo + CV_B_HI + off, in_hi + so, sz);
            cp16(bo + CV_B_LO + off, in_lo + so, sz);
        }
    };

    issue(0); CP_COMMIT();
    issue(1); CP_COMMIT();
    issue(2); CP_COMMIT();
    for (int s = 0; s < NST; s++) {
        if (s < NST - 2)       { CP_WAIT(2); }
        else if (s == NST - 2) { CP_WAIT(1); }
        else                   { CP_WAIT(0); }
        __syncthreads();
        if (s + 3 < NST) { issue(s + 3); CP_COMMIT(); }
        compute_conv(sb + (s & 3) * CV_BUF, lane, wm, wn_, c);
    }

    // epilogue
#pragma unroll
    for (int mi = 0; mi < 2; mi++) {
#pragma unroll
        for (int ni = 0; ni < 4; ni++) {
            int r0 = wm + mi * 16 + (lane >> 2);
            int colb = col0 + wn_ + ni * 8 + (lane & 3) * 2;
#pragma unroll
            for (int e = 0; e < 4; e++) {
                int row = r0 + (e >> 1) * 8;
                int col = colb + (e & 1);
                float xv = c[mi][ni][e];
                if (RELU) xv = xv > 0.f ? xv : 0.2f * xv;
                if (LAST) {
                    size_t o = (size_t)col * 256 + m0 + row;
                    g_H[o] = xv;
                    split1(xv, g_Hhi[o], g_Hlo[o]);
                } else {
                    size_t o = (size_t)col * 128 + row;
                    split1(xv, out_hi[o], out_lo[o]);
                }
            }
        }
    }
}

// ---------------- WaveNet: main+gate in one CTA, pointwise fused ------------
// grid (64, 2): col tile 32, mh = co half. 32 slabs: s<16 main, s>=16 gate.
__global__ __launch_bounds__(256, 2)
void wn_mma3(int layer, int dil) {
    extern __shared__ __align__(1024) char smem[];
    const uint32_t sb = smem_u32(smem);

    const int tid = threadIdx.x;
    const int lane = tid & 31;
    const int warp = tid >> 5;
    const int wm = (warp >> 1) * 32;
    const int wn_ = (warp & 1) * 16;
    const int col0 = blockIdx.x * 32;
    const int mh = blockIdx.y;

    float c[2][2][2][4];   // [z][mi][ni][e]
#pragma unroll
    for (int z = 0; z < 2; z++)
#pragma unroll
        for (int i = 0; i < 2; i++)
#pragma unroll
            for (int j = 0; j < 2; j++)
#pragma unroll
                for (int k = 0; k < 4; k++) c[z][i][j][k] = 0.f;

    auto issue = [&](int s) {
        const uint32_t bo = sb + (s & 3) * WN_BUF;
        const int zsel = s >> 4;
        const int local = s & 15;
        const int tap = local >> 3;
        const int ci0 = (local & 7) * 32;
        const __nv_bfloat16* whi =
            g_wnhi + ((size_t)(layer * 2 + zsel) * 256 + mh * 128) * 512;
        const __nv_bfloat16* wlo =
            g_wnlo + ((size_t)(layer * 2 + zsel) * 256 + mh * 128) * 512;
        // A: 128 rows x 64B: 512 slots
#pragma unroll
        for (int g = 0; g < 2; g++) {
            int gi = tid + g * 256;
            int row = gi >> 2, j = gi & 3;
            uint32_t off = sw64(row * 64 + j * 16);
            size_t so = (size_t)row * 512 + local * 32 + j * 8;
            cp16(bo + WN_A_HI + off, whi + so, 16);
            cp16(bo + WN_A_LO + off, wlo + so, 16);
        }
        // B: 32 rows x 64B: 128 slots
        if (tid < 128) {
            int row = tid >> 2, j = tid & 3;
            int col = col0 + row;
            int tt = col & 255;
            bool v = tap ? true : (tt >= dil);
            int scol = tap ? col : (v ? col - dil : col);
            size_t so = (size_t)scol * 256 + ci0 + j * 8;
            int sz = v ? 16 : 0;
            uint32_t off = sw64(row * 64 + j * 16);
            cp16(bo + WN_B_HI + off, g_Hhi + so, sz);
            cp16(bo + WN_B_LO + off, g_Hlo + so, sz);
        }
    };

    issue(0); CP_COMMIT();
    issue(1); CP_COMMIT();
    issue(2); CP_COMMIT();
    for (int s = 0; s < 32; s++) {
        if (s < 30)       { CP_WAIT(2); }
        else if (s == 30) { CP_WAIT(1); }
        else              { CP_WAIT(0); }
        __syncthreads();
        if (s + 3 < 32) { issue(s + 3); CP_COMMIT(); }
        compute_wn(sb + (s & 3) * WN_BUF, lane, wm, wn_, c[s >> 4]);
    }

    // fused pointwise epilogue: z = tanh(main)*sigmoid(gate); H += z
#pragma unroll
    for (int mi = 0; mi < 2; mi++) {
#pragma unroll
        for (int ni = 0; ni < 2; ni++) {
#pragma unroll
            for (int e = 0; e < 4; e++) {
                int co = mh * 128 + wm + mi * 16 + (lane >> 2) + (e >> 1) * 8;
                int col = col0 + wn_ + ni * 8 + (lane & 3) * 2 + (e & 1);
                float pm = c[0][mi][ni][e];
                float pg = c[1][mi][ni][e];
                float zv = tanhf(pm) * (1.f / (1.f + expf(-pg)));
                size_t idx = (size_t)col * 256 + co;
                float h = g_H[idx] + zv;
                g_H[idx] = h;
                split1(h, g_Hhi[idx], g_Hlo[idx]);
            }
        }
    }
}

// ---------------- stash / finalize ------------------------------------------
__global__ void stash_henc() {
    int i = blockIdx.x * 256 + threadIdx.x;         // 2048
    int b = i >> 8, co = i & 255;
    g_Henc[i] = g_H[((size_t)b * 256 + 255) * 256 + co];
}

__global__ void finalize_kernel(const float* __restrict__ jw,
                                float* __restrict__ out, int out_size) {
    __shared__ float red[256];
    const int b = blockIdx.x;
    const int t = threadIdx.x;
    float v = g_H[((size_t)b * 256 + 255) * 256 + t] - g_Henc[b * 256 + t];
    out[b * 256 + t] = v;
    red[t] = v * jw[t];
    __syncthreads();
#pragma unroll
    for (int s = 128; s > 0; s >>= 1) {
        if (t < s) red[t] += red[t + s];
        __syncthreads();
    }
    if (t == 0 && out_size >= 2048 + 8) out[2048 + b] = red[0];
}

// ---------------- launch -----------------------------------------------------
extern "C" void kernel_launch(void* const* d_in, const int* in_sizes, int n_in,
                              void* d_out, int out_size) {
    const float* x     = (const float*)d_in[0];
    const float* w0    = (const float*)d_in[1];
    const float* w123  = (const float*)d_in[2];
    const float* w4567 = (const float*)d_in[3];
    const float* w8    = (const float*)d_in[4];
    const float* wm    = (const float*)d_in[5];
    const float* wg    = (const float*)d_in[6];
    const float* jw    = (const float*)d_in[7];
    float* out = (float*)d_out;

    __nv_bfloat16 *pAhi, *pAlo, *pBhi, *pBlo;
    __nv_bfloat16 *w123hi, *w123lo, *w4567hi, *w4567lo, *w8hi, *w8lo;
    cudaGetSymbolAddress((void**)&pAhi, g_pAhi);
    cudaGetSymbolAddress((void**)&pAlo, g_pAlo);
    cudaGetSymbolAddress((void**)&pBhi, g_pBhi);
    cudaGetSymbolAddress((void**)&pBlo, g_pBlo);
    cudaGetSymbolAddress((void**)&w123hi, g_w123hi);
    cudaGetSymbolAddress((void**)&w123lo, g_w123lo);
    cudaGetSymbolAddress((void**)&w4567hi, g_w4567hi);
    cudaGetSymbolAddress((void**)&w4567lo, g_w4567lo);
    cudaGetSymbolAddress((void**)&w8hi, g_w8hi);
    cudaGetSymbolAddress((void**)&w8lo, g_w8lo);

    cudaFuncSetAttribute(conv_mma3<7,3,128,64,true ,false>, cudaFuncAttributeMaxDynamicSharedMemorySize, CV_SMEM);
    cudaFuncSetAttribute(conv_mma3<7,3, 64,32,true ,false>, cudaFuncAttributeMaxDynamicSharedMemorySize, CV_SMEM);
    cudaFuncSetAttribute(conv_mma3<7,3, 32,16,true ,false>, cudaFuncAttributeMaxDynamicSharedMemorySize, CV_SMEM);
    cudaFuncSetAttribute(conv_mma3<3,1, 16, 8,true ,false>, cudaFuncAttributeMaxDynamicSharedMemorySize, CV_SMEM);
    cudaFuncSetAttribute(conv_mma3<3,1,  8, 4,true ,false>, cudaFuncAttributeMaxDynamicSharedMemorySize, CV_SMEM);
    cudaFuncSetAttribute(conv_mma3<3,1,  4, 2,true ,false>, cudaFuncAttributeMaxDynamicSharedMemorySize, CV_SMEM);
    cudaFuncSetAttribute(conv_mma3<3,1,  2, 1,true ,false>, cudaFuncAttributeMaxDynamicSharedMemorySize, CV_SMEM);
    cudaFuncSetAttribute(conv_mma3<1,0,  1, 1,false,true >, cudaFuncAttributeMaxDynamicSharedMemorySize, CV_SMEM);
    cudaFuncSetAttribute(wn_mma3, cudaFuncAttributeMaxDynamicSharedMemorySize, WN_SMEM);

    prep_weights<<<512, 256>>>(w123, w4567, w8, wm, wg);
    conv0_kernel<<<NFRAMES, 256>>>(x, w0);

    // (KW,PAD,LIN,LOUT,RELU,LAST); grid = (NFRAMES*LOUT/64, COUT/128)
    conv_mma3<7,3,128,64,true ,false><<<dim3(2048,1), 256, CV_SMEM>>>(pAhi, pAlo, w123hi,              w123lo,              pBhi, pBlo);
    conv_mma3<7,3, 64,32,true ,false><<<dim3(1024,1), 256, CV_SMEM>>>(pBhi, pBlo, w123hi + 1*128*896,  w123lo + 1*128*896,  pAhi, pAlo);
    conv_mma3<7,3, 32,16,true ,false><<<dim3( 512,1), 256, CV_SMEM>>>(pAhi, pAlo, w123hi + 2*128*896,  w123lo + 2*128*896,  pBhi, pBlo);
    conv_mma3<3,1, 16, 8,true ,false><<<dim3( 256,1), 256, CV_SMEM>>>(pBhi, pBlo, w4567hi,             w4567lo,             pAhi, pAlo);
    conv_mma3<3,1,  8, 4,true ,false><<<dim3( 128,1), 256, CV_SMEM>>>(pAhi, pAlo, w4567hi + 1*128*384, w4567lo + 1*128*384, pBhi, pBlo);
    conv_mma3<3,1,  4, 2,true ,false><<<dim3(  64,1), 256, CV_SMEM>>>(pBhi, pBlo, w4567hi + 2*128*384, w4567lo + 2*128*384, pAhi, pAlo);
    conv_mma3<3,1,  2, 1,true ,false><<<dim3(  32,1), 256, CV_SMEM>>>(pAhi, pAlo, w4567hi + 3*128*384, w4567lo + 3*128*384, pBhi, pBlo);
    conv_mma3<1,0,  1, 1,false,true ><<<dim3(  32,2), 256, CV_SMEM>>>(pBhi, pBlo, w8hi,                w8lo,                pAhi, pAlo);

    stash_henc<<<8, 256>>>();

    for (int l = 0; l < 8; l++) {
        wn_mma3<<<dim3(64, 2), 256, WN_SMEM>>>(l, 1 << l);
    }

    finalize_kernel<<<8, 256>>>(jw, out, out_size);
}

// round 9
// speedup vs baseline: 1.2732x; 1.2732x over previous
#include <cuda_runtime.h>
#include <cuda_bf16.h>
#include <cstdint>
#include <math.h>

// ============================================================================
// ARDiscriminator on GB300 — round 8: R4 base (637us) with a single change:
// single-barrier-per-slab pipeline with mid-compute fill issue.
// bf16 hi/lo 3-term split; 128x64 tiles; 64-wide K slabs; 2 CTAs/SM.
// ============================================================================

#define NFRAMES 2048

template <int N> struct ILog2 { static constexpr int v = 1 + ILog2<N / 2>::v; };
template <> struct ILog2<1> { static constexpr int v = 0; };

// ---------------- static scratch -------------------------------------------
__device__ __align__(128) __nv_bfloat16 g_pAhi[(size_t)NFRAMES * 128 * 128];
__device__ __align__(128) __nv_bfloat16 g_pAlo[(size_t)NFRAMES * 128 * 128];
__device__ __align__(128) __nv_bfloat16 g_pBhi[(size_t)NFRAMES * 64 * 128];
__device__ __align__(128) __nv_bfloat16 g_pBlo[(size_t)NFRAMES * 64 * 128];
__device__ __align__(128) float         g_H   [NFRAMES * 256];
__device__ __align__(128) __nv_bfloat16 g_Hhi [NFRAMES * 256];
__device__ __align__(128) __nv_bfloat16 g_Hlo [NFRAMES * 256];
__device__ __align__(128) float         g_pre [2 * NFRAMES * 256];
__device__ __align__(128) float         g_Henc[2048];
// weight planes (k-reordered: k = kw*CIN + ci ; tap*256+ci for wavenet)
__device__ __align__(128) __nv_bfloat16 g_w123hi [3 * 128 * 896];
__device__ __align__(128) __nv_bfloat16 g_w123lo [3 * 128 * 896];
__device__ __align__(128) __nv_bfloat16 g_w4567hi[4 * 128 * 384];
__device__ __align__(128) __nv_bfloat16 g_w4567lo[4 * 128 * 384];
__device__ __align__(128) __nv_bfloat16 g_w8hi   [256 * 128];
__device__ __align__(128) __nv_bfloat16 g_w8lo   [256 * 128];
__device__ __align__(128) __nv_bfloat16 g_wnhi   [8 * 2 * 256 * 512];
__device__ __align__(128) __nv_bfloat16 g_wnlo   [8 * 2 * 256 * 512];

// ---------------- low-level helpers ----------------------------------------
__device__ __forceinline__ uint32_t smem_u32(const void* p) {
    uint32_t a;
    asm("{ .reg .u64 t; cvta.to.shared.u64 t, %1; cvt.u32.u64 %0, t; }"
        : "=r"(a) : "l"(p));
    return a;
}
__device__ __forceinline__ void cp16(uint32_t dst, const void* src, int sz) {
    asm volatile("cp.async.cg.shared.global [%0], [%1], 16, %2;"
                 :: "r"(dst), "l"(src), "r"(sz));
}
#define CP_COMMIT() asm volatile("cp.async.commit_group;")
#define CP_WAIT(n)  asm volatile("cp.async.wait_group %0;" :: "n"(n))

__device__ __forceinline__ void ldsm_x4(uint32_t (&r)[4], uint32_t addr) {
    asm volatile("ldmatrix.sync.aligned.m8n8.x4.shared.b16 {%0,%1,%2,%3}, [%4];"
                 : "=r"(r[0]), "=r"(r[1]), "=r"(r[2]), "=r"(r[3]) : "r"(addr));
}
__device__ __forceinline__ void ldsm_x2(uint32_t (&r)[2], uint32_t addr) {
    asm volatile("ldmatrix.sync.aligned.m8n8.x2.shared.b16 {%0,%1}, [%2];"
                 : "=r"(r[0]), "=r"(r[1]) : "r"(addr));
}
__device__ __forceinline__ void mma_bf16(float (&c)[4], const uint32_t (&a)[4],
                                         uint32_t b0, uint32_t b1) {
    asm volatile(
        "mma.sync.aligned.m16n8k16.row.col.f32.bf16.bf16.f32 "
        "{%0,%1,%2,%3}, {%4,%5,%6,%7}, {%8,%9}, {%0,%1,%2,%3};"
        : "+f"(c[0]), "+f"(c[1]), "+f"(c[2]), "+f"(c[3])
        : "r"(a[0]), "r"(a[1]), "r"(a[2]), "r"(a[3]), "r"(b0), "r"(b1));
}

__device__ __forceinline__ int sw128(int off) { return off ^ ((off >> 3) & 0x70); }

__device__ __forceinline__ void split1(float v, __nv_bfloat16& h, __nv_bfloat16& l) {
    h = __float2bfloat16(v);
    l = __float2bfloat16(v - __bfloat162float(h));
}

// SMEM tile offsets within one pipeline buffer (identical to R4/637us)
static constexpr int SM_A_HI = 0;
static constexpr int SM_A_LO = 16384;
static constexpr int SM_B_HI = 32768;
static constexpr int SM_B_LO = 40960;
static constexpr int BUFSZ   = 49152;
static constexpr int SMEM_PIPE = 2 * BUFSZ;  // 96KB dynamic

// one 16-wide K chunk of the 3-term split warp-tile compute (32M x 32N)
__device__ __forceinline__ void compute_kc(uint32_t base, int lane, int wm, int wn_,
                                           int kc, float (&c)[2][4][4]) {
    uint32_t bh[4][2], bl[4][2];
#pragma unroll
    for (int ni = 0; ni < 4; ni++) {
        int off = (wn_ + ni * 8 + (lane & 7)) * 128 +
                  (kc + ((lane >> 3) & 1) * 8) * 2;
        int swo = sw128(off);
        ldsm_x2(bh[ni], base + SM_B_HI + swo);
        ldsm_x2(bl[ni], base + SM_B_LO + swo);
    }
#pragma unroll
    for (int mi = 0; mi < 2; mi++) {
        int off = (wm + mi * 16 + (lane & 7) + ((lane >> 3) & 1) * 8) * 128 +
                  (kc + (lane >> 4) * 8) * 2;
        int swo = sw128(off);
        uint32_t ah[4], al[4];
        ldsm_x4(ah, base + SM_A_HI + swo);
        ldsm_x4(al, base + SM_A_LO + swo);
#pragma unroll
        for (int ni = 0; ni < 4; ni++) {
            mma_bf16(c[mi][ni], ah, bh[ni][0], bh[ni][1]);
            mma_bf16(c[mi][ni], ah, bl[ni][0], bl[ni][1]);
            mma_bf16(c[mi][ni], al, bh[ni][0], bh[ni][1]);
        }
    }
}

// ---------------- weight prep: split + k-reorder -----------------------------
__global__ void prep_weights(const float* __restrict__ w123,
                             const float* __restrict__ w4567,
                             const float* __restrict__ w8,
                             const float* __restrict__ wm,
                             const float* __restrict__ wg) {
    const int stride = gridDim.x * blockDim.x;
    const int t0 = blockIdx.x * blockDim.x + threadIdx.x;
    for (int e = t0; e < 3 * 128 * 896; e += stride) {
        int l = e / (128 * 896), r = e % (128 * 896);
        int co = r / 896, k = r % 896;
        int kw = k >> 7, ci = k & 127;
        split1(w123[((l * 128 + co) * 128 + ci) * 7 + kw], g_w123hi[e], g_w123lo[e]);
    }
    for (int e = t0; e < 4 * 128 * 384; e += stride) {
        int l = e / (128 * 384), r = e % (128 * 384);
        int co = r / 384, k = r % 384;
        int kw = k >> 7, ci = k & 127;
        split1(w4567[((l * 128 + co) * 128 + ci) * 3 + kw], g_w4567hi[e], g_w4567lo[e]);
    }
    for (int e = t0; e < 256 * 128; e += stride) {
        int co = e >> 7, ci = e & 127;
        split1(w8[co * 128 + ci], g_w8hi[e], g_w8lo[e]);
    }
    for (int e = t0; e < 8 * 2 * 256 * 512; e += stride) {
        int lz = e / (256 * 512), r = e % (256 * 512);
        int co = r / 512, k = r % 512;
        int tap = k >> 8, ci = k & 255;
        int l = lz >> 1, z = lz & 1;
        const float* w = z ? wg : wm;
        split1(w[((l * 256 + co) * 256 + ci) * 2 + tap], g_wnhi[e], g_wnlo[e]);
    }
}

// ---------------- encoder conv0 (Cin=1, K=7, s=2, pad 3) --------------------
__global__ void conv0_kernel(const float* __restrict__ x,
                             const float* __restrict__ w0) {
    __shared__ float xin[256];
    __shared__ float w0s[896];
    const int f = blockIdx.x;
    const int b = f >> 8, t = (f & 255) + 256;
    const int tid = threadIdx.x;

    xin[tid] = x[(b * 256 + tid) * 512 + t];
    for (int i = tid; i < 896; i += 256) w0s[i] = w0[i];
    __syncthreads();

    const int co = tid & 127;
    const int ph = tid >> 7;
#pragma unroll 4
    for (int u = 0; u < 64; u++) {
        int p = ph * 64 + u;
        float s = 0.f;
#pragma unroll
        for (int k = 0; k < 7; k++) {
            int ip = 2 * p + k - 3;
            float xv = (ip >= 0 && ip < 256) ? xin[ip] : 0.f;
            s = fmaf(w0s[co * 7 + k], xv, s);
        }
        s = s > 0.f ? s : 0.2f * s;
        size_t o = ((size_t)f * 128 + p) * 128 + co;
        split1(s, g_pAhi[o], g_pAlo[o]);
    }
}

// ---------------- conv-as-GEMM: 128x64, single-sync 2-stage pipeline --------
template <int KW, int PAD, int LIN, int LOUT, bool RELU, bool LAST>
__global__ __launch_bounds__(256, 2)
void conv_mma2(const __nv_bfloat16* __restrict__ in_hi,
               const __nv_bfloat16* __restrict__ in_lo,
               const __nv_bfloat16* __restrict__ w_hi,
               const __nv_bfloat16* __restrict__ w_lo,
               __nv_bfloat16* __restrict__ out_hi,
               __nv_bfloat16* __restrict__ out_lo) {
    constexpr int K = KW * 128;
    constexpr int NST = K / 64;
    constexpr int LOG = ILog2<LOUT>::v;
    extern __shared__ __align__(1024) char smem[];
    const uint32_t sb = smem_u32(smem);

    const int tid = threadIdx.x;
    const int lane = tid & 31;
    const int warp = tid >> 5;
    const int wm = (warp >> 1) * 32;
    const int wn_ = (warp & 1) * 32;
    const int col0 = blockIdx.x * 64;
    const int m0 = blockIdx.y * 128;

    float c[2][4][4];
#pragma unroll
    for (int i = 0; i < 2; i++)
#pragma unroll
        for (int j = 0; j < 4; j++)
#pragma unroll
            for (int k = 0; k < 4; k++) c[i][j][k] = 0.f;

    auto issue = [&](int s) {
        const uint32_t bo = sb + (s & 1) * BUFSZ;
        const int kw = s >> 1;
        const int ci0 = (s & 1) * 64;
        // A tile: 128 rows x 128B (weights, k-contiguous)
#pragma unroll
        for (int g = 0; g < 4; g++) {
            int gi = tid + g * 256;
            int row = gi >> 3, j = gi & 7;
            uint32_t off = row * 128 + ((j ^ (row & 7)) << 4);
            size_t so = (size_t)(m0 + row) * K + s * 64 + j * 8;
            cp16(bo + SM_A_HI + off, w_hi + so, 16);
            cp16(bo + SM_A_LO + off, w_lo + so, 16);
        }
        // B tile: 64 rows x 128B (im2col, ci-contiguous)
#pragma unroll
        for (int g = 0; g < 2; g++) {
            int gi = tid + g * 256;
            int row = gi >> 3, j = gi & 7;
            int col = col0 + row;
            int f = col >> LOG;
            int p = col & (LOUT - 1);
            int ip = 2 * p + kw - PAD;
            bool v = ((unsigned)ip < (unsigned)LIN);
            size_t so = ((size_t)f * LIN + (v ? ip : 0)) * 128 + ci0 + j * 8;
            int sz = v ? 16 : 0;
            uint32_t off = row * 128 + ((j ^ (row & 7)) << 4);
            cp16(bo + SM_B_HI + off, in_hi + so, sz);
            cp16(bo + SM_B_LO + off, in_lo + so, sz);
        }
    };

    issue(0); CP_COMMIT();
    for (int s = 0; s < NST; s++) {
        CP_WAIT(0);
        __syncthreads();          // tile s ready; all warps done with compute(s-1)
        const uint32_t base = sb + (s & 1) * BUFSZ;
        compute_kc(base, lane, wm, wn_, 0, c);
        if (s + 1 < NST) { issue(s + 1); CP_COMMIT(); }   // overlaps kc=16..48
        compute_kc(base, lane, wm, wn_, 16, c);
        compute_kc(base, lane, wm, wn_, 32, c);
        compute_kc(base, lane, wm, wn_, 48, c);
    }

    // epilogue: write hi/lo planes (channel-last) or H (+planes) for LAST
#pragma unroll
    for (int mi = 0; mi < 2; mi++) {
#pragma unroll
        for (int ni = 0; ni < 4; ni++) {
            int r0 = wm + mi * 16 + (lane >> 2);
            int colb = col0 + wn_ + ni * 8 + (lane & 3) * 2;
#pragma unroll
            for (int e = 0; e < 4; e++) {
                int row = r0 + (e >> 1) * 8;
                int col = colb + (e & 1);
                float xv = c[mi][ni][e];
                if (RELU) xv = xv > 0.f ? xv : 0.2f * xv;
                if (LAST) {
                    size_t o = (size_t)col * 256 + m0 + row;
                    g_H[o] = xv;
                    split1(xv, g_Hhi[o], g_Hlo[o]);
                } else {
                    size_t o = (size_t)col * 128 + row;
                    split1(xv, out_hi[o], out_lo[o]);
                }
            }
        }
    }
}

// ---------------- WaveNet GEMM (main+gate), K = 512 (tap-major) -------------
__global__ __launch_bounds__(256, 2)
void wn_mma2(int layer, int dil) {
    extern __shared__ __align__(1024) char smem[];
    const uint32_t sb = smem_u32(smem);

    const int tid = threadIdx.x;
    const int lane = tid & 31;
    const int warp = tid >> 5;
    const int wm = (warp >> 1) * 32;
    const int wn_ = (warp & 1) * 32;
    const int col0 = blockIdx.x * 64;
    const int z = blockIdx.y >> 1;
    const int mh = blockIdx.y & 1;
    const __nv_bfloat16* w_hi = g_wnhi + ((size_t)(layer * 2 + z) * 256 + mh * 128) * 512;
    const __nv_bfloat16* w_lo = g_wnlo + ((size_t)(layer * 2 + z) * 256 + mh * 128) * 512;

    float c[2][4][4];
#pragma unroll
    for (int i = 0; i < 2; i++)
#pragma unroll
        for (int j = 0; j < 4; j++)
#pragma unroll
            for (int k = 0; k < 4; k++) c[i][j][k] = 0.f;

    auto issue = [&](int s) {
        const uint32_t bo = sb + (s & 1) * BUFSZ;
        const int tap = s >> 2;
        const int ci0 = (s & 3) * 64;
#pragma unroll
        for (int g = 0; g < 4; g++) {
            int gi = tid + g * 256;
            int row = gi >> 3, j = gi & 7;
            uint32_t off = row * 128 + ((j ^ (row & 7)) << 4);
            size_t so = (size_t)row * 512 + s * 64 + j * 8;
            cp16(bo + SM_A_HI + off, w_hi + so, 16);
            cp16(bo + SM_A_LO + off, w_lo + so, 16);
        }
#pragma unroll
        for (int g = 0; g < 2; g++) {
            int gi = tid + g * 256;
            int row = gi >> 3, j = gi & 7;
            int col = col0 + row;
            int tt = col & 255;
            bool v = tap ? true : (tt >= dil);
            int scol = tap ? col : (v ? col - dil : col);
            size_t so = (size_t)scol * 256 + ci0 + j * 8;
            int sz = v ? 16 : 0;
            uint32_t off = row * 128 + ((j ^ (row & 7)) << 4);
            cp16(bo + SM_B_HI + off, g_Hhi + so, sz);
            cp16(bo + SM_B_LO + off, g_Hlo + so, sz);
        }
    };

    issue(0); CP_COMMIT();
    for (int s = 0; s < 8; s++) {
        CP_WAIT(0);
        __syncthreads();
        const uint32_t base = sb + (s & 1) * BUFSZ;
        compute_kc(base, lane, wm, wn_, 0, c);
        if (s + 1 < 8) { issue(s + 1); CP_COMMIT(); }
        compute_kc(base, lane, wm, wn_, 16, c);
        compute_kc(base, lane, wm, wn_, 32, c);
        compute_kc(base, lane, wm, wn_, 48, c);
    }

    float* pre = g_pre + (size_t)z * NFRAMES * 256;
#pragma unroll
    for (int mi = 0; mi < 2; mi++) {
#pragma unroll
        for (int ni = 0; ni < 4; ni++) {
            int r0 = mh * 128 + wm + mi * 16 + (lane >> 2);
            int colb = col0 + wn_ + ni * 8 + (lane & 3) * 2;
#pragma unroll
            for (int e = 0; e < 4; e++) {
                int row = r0 + (e >> 1) * 8;
                int col = colb + (e & 1);
                pre[(size_t)col * 256 + row] = c[mi][ni][e];
            }
        }
    }
}

// ---------------- pointwise / stash / finalize ------------------------------
__global__ void wn_pointwise() {
    int idx = blockIdx.x * 256 + threadIdx.x;       // 524288
    float pm = g_pre[idx];
    float pg = g_pre[NFRAMES * 256 + idx];
    float zv = tanhf(pm) * (1.f / (1.f + expf(-pg)));
    float h = g_H[idx] + zv;
    g_H[idx] = h;
    split1(h, g_Hhi[idx], g_Hlo[idx]);
}

__global__ void stash_henc() {
    int i = blockIdx.x * 256 + threadIdx.x;         // 2048
    int b = i >> 8, co = i & 255;
    g_Henc[i] = g_H[((size_t)b * 256 + 255) * 256 + co];
}

__global__ void finalize_kernel(const float* __restrict__ jw,
                                float* __restrict__ out, int out_size) {
    __shared__ float red[256];
    const int b = blockIdx.x;
    const int t = threadIdx.x;
    float v = g_H[((size_t)b * 256 + 255) * 256 + t] - g_Henc[b * 256 + t];
    out[b * 256 + t] = v;
    red[t] = v * jw[t];
    __syncthreads();
#pragma unroll
    for (int s = 128; s > 0; s >>= 1) {
        if (t < s) red[t] += red[t + s];
        __syncthreads();
    }
    if (t == 0 && out_size >= 2048 + 8) out[2048 + b] = red[0];
}

// ---------------- launch -----------------------------------------------------
extern "C" void kernel_launch(void* const* d_in, const int* in_sizes, int n_in,
                              void* d_out, int out_size) {
    const float* x     = (const float*)d_in[0];
    const float* w0    = (const float*)d_in[1];
    const float* w123  = (const float*)d_in[2];
    const float* w4567 = (const float*)d_in[3];
    const float* w8    = (const float*)d_in[4];
    const float* wm    = (const float*)d_in[5];
    const float* wg    = (const float*)d_in[6];
    const float* jw    = (const float*)d_in[7];
    float* out = (float*)d_out;

    __nv_bfloat16 *pAhi, *pAlo, *pBhi, *pBlo;
    __nv_bfloat16 *w123hi, *w123lo, *w4567hi, *w4567lo, *w8hi, *w8lo;
    cudaGetSymbolAddress((void**)&pAhi, g_pAhi);
    cudaGetSymbolAddress((void**)&pAlo, g_pAlo);
    cudaGetSymbolAddress((void**)&pBhi, g_pBhi);
    cudaGetSymbolAddress((void**)&pBlo, g_pBlo);
    cudaGetSymbolAddress((void**)&w123hi, g_w123hi);
    cudaGetSymbolAddress((void**)&w123lo, g_w123lo);
    cudaGetSymbolAddress((void**)&w4567hi, g_w4567hi);
    cudaGetSymbolAddress((void**)&w4567lo, g_w4567lo);
    cudaGetSymbolAddress((void**)&w8hi, g_w8hi);
    cudaGetSymbolAddress((void**)&w8lo, g_w8lo);

    cudaFuncSetAttribute(conv_mma2<7,3,128,64,true ,false>, cudaFuncAttributeMaxDynamicSharedMemorySize, SMEM_PIPE);
    cudaFuncSetAttribute(conv_mma2<7,3, 64,32,true ,false>, cudaFuncAttributeMaxDynamicSharedMemorySize, SMEM_PIPE);
    cudaFuncSetAttribute(conv_mma2<7,3, 32,16,true ,false>, cudaFuncAttributeMaxDynamicSharedMemorySize, SMEM_PIPE);
    cudaFuncSetAttribute(conv_mma2<3,1, 16, 8,true ,false>, cudaFuncAttributeMaxDynamicSharedMemorySize, SMEM_PIPE);
    cudaFuncSetAttribute(conv_mma2<3,1,  8, 4,true ,false>, cudaFuncAttributeMaxDynamicSharedMemorySize, SMEM_PIPE);
    cudaFuncSetAttribute(conv_mma2<3,1,  4, 2,true ,false>, cudaFuncAttributeMaxDynamicSharedMemorySize, SMEM_PIPE);
    cudaFuncSetAttribute(conv_mma2<3,1,  2, 1,true ,false>, cudaFuncAttributeMaxDynamicSharedMemorySize, SMEM_PIPE);
    cudaFuncSetAttribute(conv_mma2<1,0,  1, 1,false,true >, cudaFuncAttributeMaxDynamicSharedMemorySize, SMEM_PIPE);
    cudaFuncSetAttribute(wn_mma2, cudaFuncAttributeMaxDynamicSharedMemorySize, SMEM_PIPE);

    prep_weights<<<512, 256>>>(w123, w4567, w8, wm, wg);
    conv0_kernel<<<NFRAMES, 256>>>(x, w0);

    // (KW,PAD,LIN,LOUT,RELU,LAST); grid = (NFRAMES*LOUT/64, COUT/128)
    conv_mma2<7,3,128,64,true ,false><<<dim3(2048,1), 256, SMEM_PIPE>>>(pAhi, pAlo, w123hi,              w123lo,              pBhi, pBlo);
    conv_mma2<7,3, 64,32,true ,false><<<dim3(1024,1), 256, SMEM_PIPE>>>(pBhi, pBlo, w123hi + 1*128*896,  w123lo + 1*128*896,  pAhi, pAlo);
    conv_mma2<7,3, 32,16,true ,false><<<dim3( 512,1), 256, SMEM_PIPE>>>(pAhi, pAlo, w123hi + 2*128*896,  w123lo + 2*128*896,  pBhi, pBlo);
    conv_mma2<3,1, 16, 8,true ,false><<<dim3( 256,1), 256, SMEM_PIPE>>>(pBhi, pBlo, w4567hi,             w4567lo,             pAhi, pAlo);
    conv_mma2<3,1,  8, 4,true ,false><<<dim3( 128,1), 256, SMEM_PIPE>>>(pAhi, pAlo, w4567hi + 1*128*384, w4567lo + 1*128*384, pBhi, pBlo);
    conv_mma2<3,1,  4, 2,true ,false><<<dim3(  64,1), 256, SMEM_PIPE>>>(pBhi, pBlo, w4567hi + 2*128*384, w4567lo + 2*128*384, pAhi, pAlo);
    conv_mma2<3,1,  2, 1,true ,false><<<dim3(  32,1), 256, SMEM_PIPE>>>(pAhi, pAlo, w4567hi + 3*128*384, w4567lo + 3*128*384, pBhi, pBlo);
    conv_mma2<1,0,  1, 1,false,true ><<<dim3(  32,2), 256, SMEM_PIPE>>>(pBhi, pBlo, w8hi,                w8lo,                pAhi, pAlo);

    stash_henc<<<8, 256>>>();

    for (int l = 0; l < 8; l++) {
        wn_mma2<<<dim3(32, 4), 256, SMEM_PIPE>>>(l, 1 << l);
        wn_pointwise<<<2048, 256>>>();
    }

    finalize_kernel<<<8, 256>>>(jw, out, out_size);
}

// round 10
// speedup vs baseline: 1.3006x; 1.0215x over previous
#include <cuda_runtime.h>
#include <cuda_bf16.h>
#include <cstdint>
#include <math.h>

// ============================================================================
// ARDiscriminator on GB300 — round 9: R8 base (600us) with a single change:
// B-fragment loads via ldmatrix.x4 (2 n-frags per instruction), cutting
// per-chunk ldsm count 12 -> 8. Everything else identical to R8.
// ============================================================================

#define NFRAMES 2048

template <int N> struct ILog2 { static constexpr int v = 1 + ILog2<N / 2>::v; };
template <> struct ILog2<1> { static constexpr int v = 0; };

// ---------------- static scratch -------------------------------------------
__device__ __align__(128) __nv_bfloat16 g_pAhi[(size_t)NFRAMES * 128 * 128];
__device__ __align__(128) __nv_bfloat16 g_pAlo[(size_t)NFRAMES * 128 * 128];
__device__ __align__(128) __nv_bfloat16 g_pBhi[(size_t)NFRAMES * 64 * 128];
__device__ __align__(128) __nv_bfloat16 g_pBlo[(size_t)NFRAMES * 64 * 128];
__device__ __align__(128) float         g_H   [NFRAMES * 256];
__device__ __align__(128) __nv_bfloat16 g_Hhi [NFRAMES * 256];
__device__ __align__(128) __nv_bfloat16 g_Hlo [NFRAMES * 256];
__device__ __align__(128) float         g_pre [2 * NFRAMES * 256];
__device__ __align__(128) float         g_Henc[2048];
// weight planes (k-reordered: k = kw*CIN + ci ; tap*256+ci for wavenet)
__device__ __align__(128) __nv_bfloat16 g_w123hi [3 * 128 * 896];
__device__ __align__(128) __nv_bfloat16 g_w123lo [3 * 128 * 896];
__device__ __align__(128) __nv_bfloat16 g_w4567hi[4 * 128 * 384];
__device__ __align__(128) __nv_bfloat16 g_w4567lo[4 * 128 * 384];
__device__ __align__(128) __nv_bfloat16 g_w8hi   [256 * 128];
__device__ __align__(128) __nv_bfloat16 g_w8lo   [256 * 128];
__device__ __align__(128) __nv_bfloat16 g_wnhi   [8 * 2 * 256 * 512];
__device__ __align__(128) __nv_bfloat16 g_wnlo   [8 * 2 * 256 * 512];

// ---------------- low-level helpers ----------------------------------------
__device__ __forceinline__ uint32_t smem_u32(const void* p) {
    uint32_t a;
    asm("{ .reg .u64 t; cvta.to.shared.u64 t, %1; cvt.u32.u64 %0, t; }"
        : "=r"(a) : "l"(p));
    return a;
}
__device__ __forceinline__ void cp16(uint32_t dst, const void* src, int sz) {
    asm volatile("cp.async.cg.shared.global [%0], [%1], 16, %2;"
                 :: "r"(dst), "l"(src), "r"(sz));
}
#define CP_COMMIT() asm volatile("cp.async.commit_group;")
#define CP_WAIT(n)  asm volatile("cp.async.wait_group %0;" :: "n"(n))

__device__ __forceinline__ void ldsm_x4(uint32_t (&r)[4], uint32_t addr) {
    asm volatile("ldmatrix.sync.aligned.m8n8.x4.shared.b16 {%0,%1,%2,%3}, [%4];"
                 : "=r"(r[0]), "=r"(r[1]), "=r"(r[2]), "=r"(r[3]) : "r"(addr));
}
__device__ __forceinline__ void mma_bf16(float (&c)[4], const uint32_t (&a)[4],
                                         uint32_t b0, uint32_t b1) {
    asm volatile(
        "mma.sync.aligned.m16n8k16.row.col.f32.bf16.bf16.f32 "
        "{%0,%1,%2,%3}, {%4,%5,%6,%7}, {%8,%9}, {%0,%1,%2,%3};"
        : "+f"(c[0]), "+f"(c[1]), "+f"(c[2]), "+f"(c[3])
        : "r"(a[0]), "r"(a[1]), "r"(a[2]), "r"(a[3]), "r"(b0), "r"(b1));
}

__device__ __forceinline__ int sw128(int off) { return off ^ ((off >> 3) & 0x70); }

__device__ __forceinline__ void split1(float v, __nv_bfloat16& h, __nv_bfloat16& l) {
    h = __float2bfloat16(v);
    l = __float2bfloat16(v - __bfloat162float(h));
}

// SMEM tile offsets within one pipeline buffer (identical to R8)
static constexpr int SM_A_HI = 0;
static constexpr int SM_A_LO = 16384;
static constexpr int SM_B_HI = 32768;
static constexpr int SM_B_LO = 40960;
static constexpr int BUFSZ   = 49152;
static constexpr int SMEM_PIPE = 2 * BUFSZ;  // 96KB dynamic

// one 16-wide K chunk of the 3-term split warp-tile compute (32M x 32N)
// B frags now via ldmatrix.x4: lanes 0-7 (col0,k0), 8-15 (col0,k8),
// 16-23 (col+8,k0), 24-31 (col+8,k8) => {b0,b1} for ni and ni+1.
__device__ __forceinline__ void compute_kc(uint32_t base, int lane, int wm, int wn_,
                                           int kc, float (&c)[2][4][4]) {
    uint32_t bh[4][2], bl[4][2];
#pragma unroll
    for (int pr = 0; pr < 2; pr++) {          // ni pairs {0,1}, {2,3}
        int off = (wn_ + pr * 16 + ((lane >> 4) & 1) * 8 + (lane & 7)) * 128 +
                  (kc + ((lane >> 3) & 1) * 8) * 2;
        int swo = sw128(off);
        uint32_t th[4], tl[4];
        ldsm_x4(th, base + SM_B_HI + swo);
        ldsm_x4(tl, base + SM_B_LO + swo);
        bh[pr * 2][0] = th[0]; bh[pr * 2][1] = th[1];
        bh[pr * 2 + 1][0] = th[2]; bh[pr * 2 + 1][1] = th[3];
        bl[pr * 2][0] = tl[0]; bl[pr * 2][1] = tl[1];
        bl[pr * 2 + 1][0] = tl[2]; bl[pr * 2 + 1][1] = tl[3];
    }
#pragma unroll
    for (int mi = 0; mi < 2; mi++) {
        int off = (wm + mi * 16 + (lane & 7) + ((lane >> 3) & 1) * 8) * 128 +
                  (kc + (lane >> 4) * 8) * 2;
        int swo = sw128(off);
        uint32_t ah[4], al[4];
        ldsm_x4(ah, base + SM_A_HI + swo);
        ldsm_x4(al, base + SM_A_LO + swo);
#pragma unroll
        for (int ni = 0; ni < 4; ni++) {
            mma_bf16(c[mi][ni], ah, bh[ni][0], bh[ni][1]);
            mma_bf16(c[mi][ni], ah, bl[ni][0], bl[ni][1]);
            mma_bf16(c[mi][ni], al, bh[ni][0], bh[ni][1]);
        }
    }
}

// ---------------- weight prep: split + k-reorder -----------------------------
__global__ void prep_weights(const float* __restrict__ w123,
                             const float* __restrict__ w4567,
                             const float* __restrict__ w8,
                             const float* __restrict__ wm,
                             const float* __restrict__ wg) {
    const int stride = gridDim.x * blockDim.x;
    const int t0 = blockIdx.x * blockDim.x + threadIdx.x;
    for (int e = t0; e < 3 * 128 * 896; e += stride) {
        int l = e / (128 * 896), r = e % (128 * 896);
        int co = r / 896, k = r % 896;
        int kw = k >> 7, ci = k & 127;
        split1(w123[((l * 128 + co) * 128 + ci) * 7 + kw], g_w123hi[e], g_w123lo[e]);
    }
    for (int e = t0; e < 4 * 128 * 384; e += stride) {
        int l = e / (128 * 384), r = e % (128 * 384);
        int co = r / 384, k = r % 384;
        int kw = k >> 7, ci = k & 127;
        split1(w4567[((l * 128 + co) * 128 + ci) * 3 + kw], g_w4567hi[e], g_w4567lo[e]);
    }
    for (int e = t0; e < 256 * 128; e += stride) {
        int co = e >> 7, ci = e & 127;
        split1(w8[co * 128 + ci], g_w8hi[e], g_w8lo[e]);
    }
    for (int e = t0; e < 8 * 2 * 256 * 512; e += stride) {
        int lz = e / (256 * 512), r = e % (256 * 512);
        int co = r / 512, k = r % 512;
        int tap = k >> 8, ci = k & 255;
        int l = lz >> 1, z = lz & 1;
        const float* w = z ? wg : wm;
        split1(w[((l * 256 + co) * 256 + ci) * 2 + tap], g_wnhi[e], g_wnlo[e]);
    }
}

// ---------------- encoder conv0 (Cin=1, K=7, s=2, pad 3) --------------------
__global__ void conv0_kernel(const float* __restrict__ x,
                             const float* __restrict__ w0) {
    __shared__ float xin[256];
    __shared__ float w0s[896];
    const int f = blockIdx.x;
    const int b = f >> 8, t = (f & 255) + 256;
    const int tid = threadIdx.x;

    xin[tid] = x[(b * 256 + tid) * 512 + t];
    for (int i = tid; i < 896; i += 256) w0s[i] = w0[i];
    __syncthreads();

    const int co = tid & 127;
    const int ph = tid >> 7;
#pragma unroll 4
    for (int u = 0; u < 64; u++) {
        int p = ph * 64 + u;
        float s = 0.f;
#pragma unroll
        for (int k = 0; k < 7; k++) {
            int ip = 2 * p + k - 3;
            float xv = (ip >= 0 && ip < 256) ? xin[ip] : 0.f;
            s = fmaf(w0s[co * 7 + k], xv, s);
        }
        s = s > 0.f ? s : 0.2f * s;
        size_t o = ((size_t)f * 128 + p) * 128 + co;
        split1(s, g_pAhi[o], g_pAlo[o]);
    }
}

// ---------------- conv-as-GEMM: 128x64, single-sync 2-stage pipeline --------
template <int KW, int PAD, int LIN, int LOUT, bool RELU, bool LAST>
__global__ __launch_bounds__(256, 2)
void conv_mma2(const __nv_bfloat16* __restrict__ in_hi,
               const __nv_bfloat16* __restrict__ in_lo,
               const __nv_bfloat16* __restrict__ w_hi,
               const __nv_bfloat16* __restrict__ w_lo,
               __nv_bfloat16* __restrict__ out_hi,
               __nv_bfloat16* __restrict__ out_lo) {
    constexpr int K = KW * 128;
    constexpr int NST = K / 64;
    constexpr int LOG = ILog2<LOUT>::v;
    extern __shared__ __align__(1024) char smem[];
    const uint32_t sb = smem_u32(smem);

    const int tid = threadIdx.x;
    const int lane = tid & 31;
    const int warp = tid >> 5;
    const int wm = (warp >> 1) * 32;
    const int wn_ = (warp & 1) * 32;
    const int col0 = blockIdx.x * 64;
    const int m0 = blockIdx.y * 128;

    float c[2][4][4];
#pragma unroll
    for (int i = 0; i < 2; i++)
#pragma unroll
        for (int j = 0; j < 4; j++)
#pragma unroll
            for (int k = 0; k < 4; k++) c[i][j][k] = 0.f;

    auto issue = [&](int s) {
        const uint32_t bo = sb + (s & 1) * BUFSZ;
        const int kw = s >> 1;
        const int ci0 = (s & 1) * 64;
        // A tile: 128 rows x 128B (weights, k-contiguous)
#pragma unroll
        for (int g = 0; g < 4; g++) {
            int gi = tid + g * 256;
            int row = gi >> 3, j = gi & 7;
            uint32_t off = row * 128 + ((j ^ (row & 7)) << 4);
            size_t so = (size_t)(m0 + row) * K + s * 64 + j * 8;
            cp16(bo + SM_A_HI + off, w_hi + so, 16);
            cp16(bo + SM_A_LO + off, w_lo + so, 16);
        }
        // B tile: 64 rows x 128B (im2col, ci-contiguous)
#pragma unroll
        for (int g = 0; g < 2; g++) {
            int gi = tid + g * 256;
            int row = gi >> 3, j = gi & 7;
            int col = col0 + row;
            int f = col >> LOG;
            int p = col & (LOUT - 1);
            int ip = 2 * p + kw - PAD;
            bool v = ((unsigned)ip < (unsigned)LIN);
            size_t so = ((size_t)f * LIN + (v ? ip : 0)) * 128 + ci0 + j * 8;
            int sz = v ? 16 : 0;
            uint32_t off = row * 128 + ((j ^ (row & 7)) << 4);
            cp16(bo + SM_B_HI + off, in_hi + so, sz);
            cp16(bo + SM_B_LO + off, in_lo + so, sz);
        }
    };

    issue(0); CP_COMMIT();
    for (int s = 0; s < NST; s++) {
        CP_WAIT(0);
        __syncthreads();          // tile s ready; all warps done with compute(s-1)
        const uint32_t base = sb + (s & 1) * BUFSZ;
        compute_kc(base, lane, wm, wn_, 0, c);
        if (s + 1 < NST) { issue(s + 1); CP_COMMIT(); }   // overlaps kc=16..48
        compute_kc(base, lane, wm, wn_, 16, c);
        compute_kc(base, lane, wm, wn_, 32, c);
        compute_kc(base, lane, wm, wn_, 48, c);
    }

    // epilogue: write hi/lo planes (channel-last) or H (+planes) for LAST
#pragma unroll
    for (int mi = 0; mi < 2; mi++) {
#pragma unroll
        for (int ni = 0; ni < 4; ni++) {
            int r0 = wm + mi * 16 + (lane >> 2);
            int colb = col0 + wn_ + ni * 8 + (lane & 3) * 2;
#pragma unroll
            for (int e = 0; e < 4; e++) {
                int row = r0 + (e >> 1) * 8;
                int col = colb + (e & 1);
                float xv = c[mi][ni][e];
                if (RELU) xv = xv > 0.f ? xv : 0.2f * xv;
                if (LAST) {
                    size_t o = (size_t)col * 256 + m0 + row;
                    g_H[o] = xv;
                    split1(xv, g_Hhi[o], g_Hlo[o]);
                } else {
                    size_t o = (size_t)col * 128 + row;
                    split1(xv, out_hi[o], out_lo[o]);
                }
            }
        }
    }
}

// ---------------- WaveNet GEMM (main+gate), K = 512 (tap-major) -------------
__global__ __launch_bounds__(256, 2)
void wn_mma2(int layer, int dil) {
    extern __shared__ __align__(1024) char smem[];
    const uint32_t sb = smem_u32(smem);

    const int tid = threadIdx.x;
    const int lane = tid & 31;
    const int warp = tid >> 5;
    const int wm = (warp >> 1) * 32;
    const int wn_ = (warp & 1) * 32;
    const int col0 = blockIdx.x * 64;
    const int z = blockIdx.y >> 1;
    const int mh = blockIdx.y & 1;
    const __nv_bfloat16* w_hi = g_wnhi + ((size_t)(layer * 2 + z) * 256 + mh * 128) * 512;
    const __nv_bfloat16* w_lo = g_wnlo + ((size_t)(layer * 2 + z) * 256 + mh * 128) * 512;

    float c[2][4][4];
#pragma unroll
    for (int i = 0; i < 2; i++)
#pragma unroll
        for (int j = 0; j < 4; j++)
#pragma unroll
            for (int k = 0; k < 4; k++) c[i][j][k] = 0.f;

    auto issue = [&](int s) {
        const uint32_t bo = sb + (s & 1) * BUFSZ;
        const int tap = s >> 2;
        const int ci0 = (s & 3) * 64;
#pragma unroll
        for (int g = 0; g < 4; g++) {
            int gi = tid + g * 256;
            int row = gi >> 3, j = gi & 7;
            uint32_t off = row * 128 + ((j ^ (row & 7)) << 4);
            size_t so = (size_t)row * 512 + s * 64 + j * 8;
            cp16(bo + SM_A_HI + off, w_hi + so, 16);
            cp16(bo + SM_A_LO + off, w_lo + so, 16);
        }
#pragma unroll
        for (int g = 0; g < 2; g++) {
            int gi = tid + g * 256;
            int row = gi >> 3, j = gi & 7;
            int col = col0 + row;
            int tt = col & 255;
            bool v = tap ? true : (tt >= dil);
            int scol = tap ? col : (v ? col - dil : col);
            size_t so = (size_t)scol * 256 + ci0 + j * 8;
            int sz = v ? 16 : 0;
            uint32_t off = row * 128 + ((j ^ (row & 7)) << 4);
            cp16(bo + SM_B_HI + off, g_Hhi + so, sz);
            cp16(bo + SM_B_LO + off, g_Hlo + so, sz);
        }
    };

    issue(0); CP_COMMIT();
    for (int s = 0; s < 8; s++) {
        CP_WAIT(0);
        __syncthreads();
        const uint32_t base = sb + (s & 1) * BUFSZ;
        compute_kc(base, lane, wm, wn_, 0, c);
        if (s + 1 < 8) { issue(s + 1); CP_COMMIT(); }
        compute_kc(base, lane, wm, wn_, 16, c);
        compute_kc(base, lane, wm, wn_, 32, c);
        compute_kc(base, lane, wm, wn_, 48, c);
    }

    float* pre = g_pre + (size_t)z * NFRAMES * 256;
#pragma unroll
    for (int mi = 0; mi < 2; mi++) {
#pragma unroll
        for (int ni = 0; ni < 4; ni++) {
            int r0 = mh * 128 + wm + mi * 16 + (lane >> 2);
            int colb = col0 + wn_ + ni * 8 + (lane & 3) * 2;
#pragma unroll
            for (int e = 0; e < 4; e++) {
                int row = r0 + (e >> 1) * 8;
                int col = colb + (e & 1);
                pre[(size_t)col * 256 + row] = c[mi][ni][e];
            }
        }
    }
}

// ---------------- pointwise / stash / finalize ------------------------------
__global__ void wn_pointwise() {
    int idx = blockIdx.x * 256 + threadIdx.x;       // 524288
    float pm = g_pre[idx];
    float pg = g_pre[NFRAMES * 256 + idx];
    float zv = tanhf(pm) * (1.f / (1.f + expf(-pg)));
    float h = g_H[idx] + zv;
    g_H[idx] = h;
    split1(h, g_Hhi[idx], g_Hlo[idx]);
}

__global__ void stash_henc() {
    int i = blockIdx.x * 256 + threadIdx.x;         // 2048
    int b = i >> 8, co = i & 255;
    g_Henc[i] = g_H[((size_t)b * 256 + 255) * 256 + co];
}

__global__ void finalize_kernel(const float* __restrict__ jw,
                                float* __restrict__ out, int out_size) {
    __shared__ float red[256];
    const int b = blockIdx.x;
    const int t = threadIdx.x;
    float v = g_H[((size_t)b * 256 + 255) * 256 + t] - g_Henc[b * 256 + t];
    out[b * 256 + t] = v;
    red[t] = v * jw[t];
    __syncthreads();
#pragma unroll
    for (int s = 128; s > 0; s >>= 1) {
        if (t < s) red[t] += red[t + s];
        __syncthreads();
    }
    if (t == 0 && out_size >= 2048 + 8) out[2048 + b] = red[0];
}

// ---------------- launch -----------------------------------------------------
extern "C" void kernel_launch(void* const* d_in, const int* in_sizes, int n_in,
                              void* d_out, int out_size) {
    const float* x     = (const float*)d_in[0];
    const float* w0    = (const float*)d_in[1];
    const float* w123  = (const float*)d_in[2];
    const float* w4567 = (const float*)d_in[3];
    const float* w8    = (const float*)d_in[4];
    const float* wm    = (const float*)d_in[5];
    const float* wg    = (const float*)d_in[6];
    const float* jw    = (const float*)d_in[7];
    float* out = (float*)d_out;

    __nv_bfloat16 *pAhi, *pAlo, *pBhi, *pBlo;
    __nv_bfloat16 *w123hi, *w123lo, *w4567hi, *w4567lo, *w8hi, *w8lo;
    cudaGetSymbolAddress((void**)&pAhi, g_pAhi);
    cudaGetSymbolAddress((void**)&pAlo, g_pAlo);
    cudaGetSymbolAddress((void**)&pBhi, g_pBhi);
    cudaGetSymbolAddress((void**)&pBlo, g_pBlo);
    cudaGetSymbolAddress((void**)&w123hi, g_w123hi);
    cudaGetSymbolAddress((void**)&w123lo, g_w123lo);
    cudaGetSymbolAddress((void**)&w4567hi, g_w4567hi);
    cudaGetSymbolAddress((void**)&w4567lo, g_w4567lo);
    cudaGetSymbolAddress((void**)&w8hi, g_w8hi);
    cudaGetSymbolAddress((void**)&w8lo, g_w8lo);

    cudaFuncSetAttribute(conv_mma2<7,3,128,64,true ,false>, cudaFuncAttributeMaxDynamicSharedMemorySize, SMEM_PIPE);
    cudaFuncSetAttribute(conv_mma2<7,3, 64,32,true ,false>, cudaFuncAttributeMaxDynamicSharedMemorySize, SMEM_PIPE);
    cudaFuncSetAttribute(conv_mma2<7,3, 32,16,true ,false>, cudaFuncAttributeMaxDynamicSharedMemorySize, SMEM_PIPE);
    cudaFuncSetAttribute(conv_mma2<3,1, 16, 8,true ,false>, cudaFuncAttributeMaxDynamicSharedMemorySize, SMEM_PIPE);
    cudaFuncSetAttribute(conv_mma2<3,1,  8, 4,true ,false>, cudaFuncAttributeMaxDynamicSharedMemorySize, SMEM_PIPE);
    cudaFuncSetAttribute(conv_mma2<3,1,  4, 2,true ,false>, cudaFuncAttributeMaxDynamicSharedMemorySize, SMEM_PIPE);
    cudaFuncSetAttribute(conv_mma2<3,1,  2, 1,true ,false>, cudaFuncAttributeMaxDynamicSharedMemorySize, SMEM_PIPE);
    cudaFuncSetAttribute(conv_mma2<1,0,  1, 1,false,true >, cudaFuncAttributeMaxDynamicSharedMemorySize, SMEM_PIPE);
    cudaFuncSetAttribute(wn_mma2, cudaFuncAttributeMaxDynamicSharedMemorySize, SMEM_PIPE);

    prep_weights<<<512, 256>>>(w123, w4567, w8, wm, wg);
    conv0_kernel<<<NFRAMES, 256>>>(x, w0);

    // (KW,PAD,LIN,LOUT,RELU,LAST); grid = (NFRAMES*LOUT/64, COUT/128)
    conv_mma2<7,3,128,64,true ,false><<<dim3(2048,1), 256, SMEM_PIPE>>>(pAhi, pAlo, w123hi,              w123lo,              pBhi, pBlo);
    conv_mma2<7,3, 64,32,true ,false><<<dim3(1024,1), 256, SMEM_PIPE>>>(pBhi, pBlo, w123hi + 1*128*896,  w123lo + 1*128*896,  pAhi, pAlo);
    conv_mma2<7,3, 32,16,true ,false><<<dim3( 512,1), 256, SMEM_PIPE>>>(pAhi, pAlo, w123hi + 2*128*896,  w123lo + 2*128*896,  pBhi, pBlo);
    conv_mma2<3,1, 16, 8,true ,false><<<dim3( 256,1), 256, SMEM_PIPE>>>(pBhi, pBlo, w4567hi,             w4567lo,             pAhi, pAlo);
    conv_mma2<3,1,  8, 4,true ,false><<<dim3( 128,1), 256, SMEM_PIPE>>>(pAhi, pAlo, w4567hi + 1*128*384, w4567lo + 1*128*384, pBhi, pBlo);
    conv_mma2<3,1,  4, 2,true ,false><<<dim3(  64,1), 256, SMEM_PIPE>>>(pBhi, pBlo, w4567hi + 2*128*384, w4567lo + 2*128*384, pAhi, pAlo);
    conv_mma2<3,1,  2, 1,true ,false><<<dim3(  32,1), 256, SMEM_PIPE>>>(pAhi, pAlo, w4567hi + 3*128*384, w4567lo + 3*128*384, pBhi, pBlo);
    conv_mma2<1,0,  1, 1,false,true ><<<dim3(  32,2), 256, SMEM_PIPE>>>(pBhi, pBlo, w8hi,                w8lo,                pAhi, pAlo);

    stash_henc<<<8, 256>>>();

    for (int l = 0; l < 8; l++) {
        wn_mma2<<<dim3(32, 4), 256, SMEM_PIPE>>>(l, 1 << l);
        wn_pointwise<<<2048, 256>>>();
    }

    finalize_kernel<<<8, 256>>>(jw, out, out_size);
}